// round 11
// baseline (speedup 1.0000x reference)
#include <cuda_runtime.h>
#include <cstdint>

// Fused binarize + fixup, 4 float4 per thread in coalesced-stride layout
// (thread t handles batch-local float4 indices inb0 + {0,256,512,768}; lanes
// contiguous per LDG.128/STG.128). Loads use __ldcs (evict-first): Pid is
// never re-read, so keeping it out of L2 leaves capacity for the 2x write
// stream. Stores keep default policy (R2 showed __stcs+bad layout regressed;
// layout was the culprit, but stores stay default as the conservative arm).
//
// All edit predicates depend only on the ORIGINAL Pid (the reference computes
// them pre-edit), and the 8 edited cells are pairwise distinct when valid, so
// each thread patches its own cells independently before storing.
__device__ __forceinline__ void apply_fix(float4& v, int inb, bool doFix,
                                          const int* rr, const int* cc,
                                          const float* vv) {
    if (!doFix) return;
    int r  = inb >> 7;          // row within batch (128 float4 per 512-col row)
    int c0 = (inb & 127) << 2;  // first column of this float4
    #pragma unroll
    for (int k = 0; k < 8; k++) {
        if (r == rr[k]) {
            int d = cc[k] - c0;
            if (d == 0) v.x = vv[k];
            else if (d == 1) v.y = vv[k];
            else if (d == 2) v.z = vv[k];
            else if (d == 3) v.w = vv[k];
        }
    }
}

__global__ __launch_bounds__(256)
void binarize_fused_kernel(const float4* __restrict__ pid4,
                           const float* __restrict__ pid,
                           const int* __restrict__ inter,
                           float4* __restrict__ out,
                           long long half4, int ncopies) {
    int bb = blockIdx.x;
    int batch = bb >> 6;                           // 64 blocks per batch
    int inb0 = ((bb & 63) << 10) | threadIdx.x;    // first float4 idx in batch
    long long base4 = (long long)batch << 16;      // batch * 65536 float4s
    long long i0 = base4 + inb0;

    // Batch all 4 loads up front (MLP=4 per thread), streaming / evict-first.
    float4 p0 = __ldcs(pid4 + i0);
    float4 p1 = __ldcs(pid4 + i0 + 256);
    float4 p2 = __ldcs(pid4 + i0 + 512);
    float4 p3 = __ldcs(pid4 + i0 + 768);

    float4 v0, v1, v2, v3;
    v0.x = p0.x > 0.f ? 1.f : 0.f; v0.y = p0.y > 0.f ? 1.f : 0.f;
    v0.z = p0.z > 0.f ? 1.f : 0.f; v0.w = p0.w > 0.f ? 1.f : 0.f;
    v1.x = p1.x > 0.f ? 1.f : 0.f; v1.y = p1.y > 0.f ? 1.f : 0.f;
    v1.z = p1.z > 0.f ? 1.f : 0.f; v1.w = p1.w > 0.f ? 1.f : 0.f;
    v2.x = p2.x > 0.f ? 1.f : 0.f; v2.y = p2.y > 0.f ? 1.f : 0.f;
    v2.z = p2.z > 0.f ? 1.f : 0.f; v2.w = p2.w > 0.f ? 1.f : 0.f;
    v3.x = p3.x > 0.f ? 1.f : 0.f; v3.y = p3.y > 0.f ? 1.f : 0.f;
    v3.z = p3.z > 0.f ? 1.f : 0.f; v3.w = p3.w > 0.f ? 1.f : 0.f;

    // Per-batch edit decision (uniform per block; same-address loads broadcast).
    int e10 = __ldg(inter + batch * 4 + 0);
    int e11 = __ldg(inter + batch * 4 + 1);
    int e20 = __ldg(inter + batch * 4 + 2);
    int e21 = __ldg(inter + batch * 4 + 3);

    bool distinct = (e10 != e11) && (e10 != e20) && (e10 != e21) &&
                    (e11 != e20) && (e11 != e21) && (e20 != e21);
    bool doFix = false;
    float oldp = 0.f;
    if (distinct) {
        long long base = (long long)batch << 18;   // batch * 512*512
        bool blocked = (__ldg(pid + base + e10 * 512 + e20) > 0.f) ||
                       (__ldg(pid + base + e11 * 512 + e21) > 0.f);
        if (!blocked) {
            doFix = true;
            oldp = (__ldg(pid + base + e10 * 512 + e11) > 0.f) ? 1.f : 0.f;
        }
    }

    int   rr[8] = {e10, e11, e20, e21, e10, e20, e11, e21};
    int   cc[8] = {e11, e10, e21, e20, e20, e10, e21, e11};
    float vv[8] = {0.f, 0.f, 0.f, 0.f, oldp, oldp, 1.f, 1.f};
    apply_fix(v0, inb0,       doFix, rr, cc, vv);
    apply_fix(v1, inb0 + 256, doFix, rr, cc, vv);
    apply_fix(v2, inb0 + 512, doFix, rr, cc, vv);
    apply_fix(v3, inb0 + 768, doFix, rr, cc, vv);

    out[i0]       = v0;
    out[i0 + 256] = v1;
    out[i0 + 512] = v2;
    out[i0 + 768] = v3;
    if (ncopies > 1) {
        long long j0 = i0 + half4;
        out[j0]       = v0;
        out[j0 + 256] = v1;
        out[j0 + 512] = v2;
        out[j0 + 768] = v3;
    }
}

extern "C" void kernel_launch(void* const* d_in, const int* in_sizes, int n_in,
                              void* d_out, int out_size) {
    const float* pid  = (const float*)d_in[0];   // (B, V, V) float32, V=512
    const int* inter  = (const int*)d_in[1];     // (B, 2, 2) int32
    float* out = (float*)d_out;

    const int V = 512;
    long long N = (long long)in_sizes[0];          // B*V*V
    int B = (int)(N / ((long long)V * V));         // 256
    int ncopies = (int)((long long)out_size / N);  // 2
    if (ncopies < 1) ncopies = 1;
    if (ncopies > 2) ncopies = 2;

    // 64 blocks per batch, 256 threads, 4 float4 per thread.
    unsigned blocks = (unsigned)B * 64u;
    binarize_fused_kernel<<<blocks, 256>>>(
        (const float4*)pid, pid, inter, (float4*)out, N / 4, ncopies);
}

// round 14
// speedup vs baseline: 1.0178x; 1.0178x over previous
#include <cuda_runtime.h>
#include <cstdint>

// Fused binarize + fixup. Measured-best config (R6): 2 float4 per thread in
// coalesced-stride layout (thread t handles batch-local float4 indices inb0
// and inb0+256; consecutive lanes hit consecutive addresses, full 128B-line
// coalescing per LDG.128/STG.128), default cache policy (both __ldcs and
// __stcs arms measured as regressions on this chip).
//
// Tweak vs R6: the small per-batch predicate loads (inter + 3 scalar Pid
// probes; uniform per block, L2-resident after the first wave) are issued
// BEFORE the bulk streaming loads, so the bulk-load latency covers them
// instead of them serializing before the stores.
//
// All edit predicates depend only on the ORIGINAL Pid (the reference computes
// them pre-edit), and the 8 edited cells are pairwise distinct when valid, so
// each thread patches its own cells independently before storing.
__device__ __forceinline__ void apply_fix(float4& v, int inb, bool doFix,
                                          const int* rr, const int* cc,
                                          const float* vv) {
    if (!doFix) return;
    int r  = inb >> 7;          // row within batch (128 float4 per 512-col row)
    int c0 = (inb & 127) << 2;  // first column of this float4
    #pragma unroll
    for (int k = 0; k < 8; k++) {
        if (r == rr[k]) {
            int d = cc[k] - c0;
            if (d == 0) v.x = vv[k];
            else if (d == 1) v.y = vv[k];
            else if (d == 2) v.z = vv[k];
            else if (d == 3) v.w = vv[k];
        }
    }
}

__global__ __launch_bounds__(256)
void binarize_fused_kernel(const float4* __restrict__ pid4,
                           const float* __restrict__ pid,
                           const int* __restrict__ inter,
                           float4* __restrict__ out,
                           long long half4, int ncopies) {
    int bb = blockIdx.x;
    int batch = bb >> 7;                           // 128 blocks per batch
    int inb0 = ((bb & 127) << 9) | threadIdx.x;    // first float4 idx in batch
    int inb1 = inb0 + 256;                         // second (coalesced stride)
    long long base4 = (long long)batch << 16;      // batch * 65536 float4s
    long long i0 = base4 + inb0;
    long long i1 = base4 + inb1;

    // --- Small uniform loads first (latency covered by bulk loads below) ---
    int e10 = __ldg(inter + batch * 4 + 0);
    int e11 = __ldg(inter + batch * 4 + 1);
    int e20 = __ldg(inter + batch * 4 + 2);
    int e21 = __ldg(inter + batch * 4 + 3);

    // --- Bulk streaming loads (MLP=2 per thread) ---
    float4 p0 = pid4[i0];
    float4 p1 = pid4[i1];

    bool distinct = (e10 != e11) && (e10 != e20) && (e10 != e21) &&
                    (e11 != e20) && (e11 != e21) && (e20 != e21);
    bool doFix = false;
    float oldp = 0.f;
    if (distinct) {
        long long base = (long long)batch << 18;   // batch * 512*512
        bool blocked = (__ldg(pid + base + e10 * 512 + e20) > 0.f) ||
                       (__ldg(pid + base + e11 * 512 + e21) > 0.f);
        if (!blocked) {
            doFix = true;
            oldp = (__ldg(pid + base + e10 * 512 + e11) > 0.f) ? 1.f : 0.f;
        }
    }

    float4 v0, v1;
    v0.x = p0.x > 0.f ? 1.f : 0.f; v0.y = p0.y > 0.f ? 1.f : 0.f;
    v0.z = p0.z > 0.f ? 1.f : 0.f; v0.w = p0.w > 0.f ? 1.f : 0.f;
    v1.x = p1.x > 0.f ? 1.f : 0.f; v1.y = p1.y > 0.f ? 1.f : 0.f;
    v1.z = p1.z > 0.f ? 1.f : 0.f; v1.w = p1.w > 0.f ? 1.f : 0.f;

    int   rr[8] = {e10, e11, e20, e21, e10, e20, e11, e21};
    int   cc[8] = {e11, e10, e21, e20, e20, e10, e21, e11};
    float vv[8] = {0.f, 0.f, 0.f, 0.f, oldp, oldp, 1.f, 1.f};
    apply_fix(v0, inb0, doFix, rr, cc, vv);
    apply_fix(v1, inb1, doFix, rr, cc, vv);

    out[i0] = v0;
    out[i1] = v1;
    if (ncopies > 1) {
        out[i0 + half4] = v0;
        out[i1 + half4] = v1;
    }
}

extern "C" void kernel_launch(void* const* d_in, const int* in_sizes, int n_in,
                              void* d_out, int out_size) {
    const float* pid  = (const float*)d_in[0];   // (B, V, V) float32, V=512
    const int* inter  = (const int*)d_in[1];     // (B, 2, 2) int32
    float* out = (float*)d_out;

    const int V = 512;
    long long N = (long long)in_sizes[0];          // B*V*V
    int B = (int)(N / ((long long)V * V));         // 256
    int ncopies = (int)((long long)out_size / N);  // 2
    if (ncopies < 1) ncopies = 1;
    if (ncopies > 2) ncopies = 2;

    // 128 blocks per batch, 256 threads, 2 float4 per thread.
    unsigned blocks = (unsigned)B * 128u;
    binarize_fused_kernel<<<blocks, 256>>>(
        (const float4*)pid, pid, inter, (float4*)out, N / 4, ncopies);
}